// round 15
// baseline (speedup 1.0000x reference)
#include <cuda_runtime.h>

#define TPB 256
#define NBLK 1400
#define VPT 3

// Device globals (zero-initialized at load; the last block of each call
// resets them -> deterministic under graph replay).
// g_sums: [0]=class, [1]=bbox, [2]=sigma, [3]=neg, [4]=n_pos
__device__ double g_sums[5];
__device__ int    g_last_pos;   // stores lastp+1 (0 == none)
__device__ unsigned int g_done; // completion ticket counter

__inline__ __device__ float warp_sum_f(float v) {
    #pragma unroll
    for (int o = 16; o > 0; o >>= 1) v += __shfl_down_sync(0xffffffffu, v, o);
    return v;
}
__inline__ __device__ int warp_sum_i(int v) {
    #pragma unroll
    for (int o = 16; o > 0; o >>= 1) v += __shfl_down_sync(0xffffffffu, v, o);
    return v;
}
__inline__ __device__ int warp_max_i(int v) {
    #pragma unroll
    for (int o = 16; o > 0; o >>= 1) v = max(v, __shfl_down_sync(0xffffffffu, v, o));
    return v;
}

// Load 3 indices starting at i0 (clamped against V; i0 assumed even so the
// int2 part is 8-byte aligned).
__inline__ __device__ void load_idx3(const int* __restrict__ vidx, int i0,
                                     int V, int& a0, int& a1, int& a2) {
    if (i0 + 2 < V) {
        int2 p = *reinterpret_cast<const int2*>(vidx + i0);
        a0 = p.x; a1 = p.y; a2 = vidx[i0 + 2];
    } else if (i0 + 1 < V) {
        int2 p = *reinterpret_cast<const int2*>(vidx + i0);
        a0 = p.x; a1 = p.y; a2 = a1;
    } else if (i0 < V) {
        a0 = vidx[i0]; a1 = a0; a2 = a0;
    } else {
        a0 = 0; a1 = 0; a2 = 0;
    }
}

__global__ void rpn_reduce_kernel(const float4* __restrict__ bbox,   // [4M]
                                  const float2* __restrict__ logits, // [4M]
                                  const float4* __restrict__ sigma,  // [4M]
                                  const float4* __restrict__ gt,     // [4M]
                                  const int* __restrict__ label,     // [4M]
                                  const int* __restrict__ vidx,      // [V]
                                  float* __restrict__ out,
                                  int V) {
    const float EPS = 1e-10f;
    float acc_c = 0.0f, acc_b = 0.0f, acc_s = 0.0f, acc_n = 0.0f;
    int npos = 0, lastp = -1;

    const int stride = gridDim.x * TPB * VPT;  // even (TPB*VPT = 768)
    int i0 = (blockIdx.x * TPB + threadIdx.x) * VPT;
    // i0 parity varies per thread; keep alignment safe: VPT=3 makes odd i0
    // possible, so use a safe int2 only when 8-aligned.
    // Simpler: scalar-safe loader below handles it via reinterpret on
    // (vidx + i0) which requires i0 even. Guard: fall back per-element when odd.

    int ia0, ia1, ia2;
    if ((i0 & 1) == 0) {
        load_idx3(vidx, i0, V, ia0, ia1, ia2);
    } else {
        ia0 = (i0 < V) ? vidx[i0] : 0;
        ia1 = (i0 + 1 < V) ? vidx[i0 + 1] : ia0;
        ia2 = (i0 + 2 < V) ? vidx[i0 + 2] : ia1;
    }

    for (; i0 < V; i0 += stride) {
        int a[VPT] = {ia0, ia1, ia2};

        // Front-batch all 15 gathers for this triple.
        int    lbl[VPT];
        float2 lg[VPT];
        float4 p[VPT], t[VPT], s[VPT];
        #pragma unroll
        for (int j = 0; j < VPT; j++) lbl[j] = label[a[j]];
        #pragma unroll
        for (int j = 0; j < VPT; j++) lg[j] = logits[a[j]];
        #pragma unroll
        for (int j = 0; j < VPT; j++) p[j] = bbox[a[j]];
        #pragma unroll
        for (int j = 0; j < VPT; j++) t[j] = gt[a[j]];
        #pragma unroll
        for (int j = 0; j < VPT; j++) s[j] = sigma[a[j]];

        // Prefetch next iteration's indices (overlaps with the math below).
        int inext = i0 + stride;
        if (inext < V) {
            if ((inext & 1) == 0) {
                load_idx3(vidx, inext, V, ia0, ia1, ia2);
            } else {
                ia0 = vidx[inext];
                ia1 = (inext + 1 < V) ? vidx[inext + 1] : ia0;
                ia2 = (inext + 2 < V) ? vidx[inext + 2] : ia1;
            }
        }

        #pragma unroll
        for (int j = 0; j < VPT; j++) {
            bool live = (i0 + j < V);
            bool pos  = (lbl[j] == 1);

            // -log_softmax at label (stable 2-class LSE)
            float m   = fmaxf(lg[j].x, lg[j].y);
            float d   = -fabsf(lg[j].x - lg[j].y);
            float lse = m + __logf(1.0f + __expf(d));
            float sel = pos ? lg[j].y : lg[j].x;
            float cls = lse - sel;

            float dx = p[j].x - t[j].x, dy = p[j].y - t[j].y,
                  dz = p[j].z - t[j].z, dw = p[j].w - t[j].w;
            float e0 = EPS + s[j].x, e1 = EPS + s[j].y,
                  e2 = EPS + s[j].z, e3 = EPS + s[j].w;
            float r0 = __fdividef(1.0f, e0), r1 = __fdividef(1.0f, e1),
                  r2 = __fdividef(1.0f, e2), r3 = __fdividef(1.0f, e3);

            float bsum = 0.5f * (dx * dx * r0 + dy * dy * r1 +
                                 dz * dz * r2 + dw * dw * r3);
            float lsum = 0.5f * (__logf(e0 * e1) + __logf(e2 * e3));
            float nsum = r0 + r1 + r2 + r3;

            if (live) {
                acc_c += cls;
                if (pos) {
                    acc_b += bsum;
                    acc_s += lsum;
                    npos++;
                    lastp = i0 + j;
                } else {
                    acc_n += nsum;
                }
            }
        }
    }

    // Block reduction in fp32 -> one double atomic per block per quantity.
    __shared__ float sh[4][TPB / 32];
    __shared__ int   shi[2][TPB / 32];
    int lane = threadIdx.x & 31;
    int wid  = threadIdx.x >> 5;

    acc_c = warp_sum_f(acc_c);
    acc_b = warp_sum_f(acc_b);
    acc_s = warp_sum_f(acc_s);
    acc_n = warp_sum_f(acc_n);
    npos  = warp_sum_i(npos);
    lastp = warp_max_i(lastp);
    if (lane == 0) {
        sh[0][wid] = acc_c; sh[1][wid] = acc_b;
        sh[2][wid] = acc_s; sh[3][wid] = acc_n;
        shi[0][wid] = npos; shi[1][wid] = lastp;
    }
    __syncthreads();
    if (wid == 0) {
        const int NW = TPB / 32;
        float c  = (lane < NW) ? sh[0][lane] : 0.0f;
        float b  = (lane < NW) ? sh[1][lane] : 0.0f;
        float s2 = (lane < NW) ? sh[2][lane] : 0.0f;
        float n2 = (lane < NW) ? sh[3][lane] : 0.0f;
        int np = (lane < NW) ? shi[0][lane] : 0;
        int lp = (lane < NW) ? shi[1][lane] : -1;
        c = warp_sum_f(c); b = warp_sum_f(b);
        s2 = warp_sum_f(s2); n2 = warp_sum_f(n2);
        np = warp_sum_i(np); lp = warp_max_i(lp);
        if (lane == 0) {
            atomicAdd(&g_sums[0], (double)c);
            atomicAdd(&g_sums[1], (double)b);
            atomicAdd(&g_sums[2], (double)s2);
            atomicAdd(&g_sums[3], (double)n2);
            atomicAdd(&g_sums[4], (double)np);
            atomicMax(&g_last_pos, lp + 1);  // lp+1 so 0 == "none"

            // Completion ticket: the LAST block finalizes.
            __threadfence();
            unsigned int ticket = atomicAdd(&g_done, 1u);
            if (ticket == gridDim.x - 1) {
                double fc = atomicAdd(&g_sums[0], 0.0);
                double fb = atomicAdd(&g_sums[1], 0.0);
                double fs = atomicAdd(&g_sums[2], 0.0);
                double fn = atomicAdd(&g_sums[3], 0.0);
                double npos_d = atomicAdd(&g_sums[4], 0.0);
                int lpf = atomicMax(&g_last_pos, 0) - 1;
                double nneg = (double)V - npos_d;

                out[0] = (float)(fc / (double)V);
                out[1] = (float)(fb / npos_d);
                out[2] = (float)(fs / npos_d);
                out[3] = (float)(fn / nneg);
                float sq = 0.0f;
                if (lpf >= 0) {
                    int aa = vidx[lpf];
                    float4 pp = bbox[aa];
                    float4 tt = gt[aa];
                    float dx = pp.x - tt.x, dy = pp.y - tt.y,
                          dz = pp.z - tt.z, dw = pp.w - tt.w;
                    sq = 0.5f * (dx * dx + dy * dy + dz * dz + dw * dw);
                }
                out[4] = (float)((double)sq / npos_d);

                // Reset globals for the next (graph-replayed) call.
                g_sums[0] = 0.0; g_sums[1] = 0.0; g_sums[2] = 0.0;
                g_sums[3] = 0.0; g_sums[4] = 0.0;
                g_last_pos = 0;
                __threadfence();
                g_done = 0u;
            }
        }
    }
}

extern "C" void kernel_launch(void* const* d_in, const int* in_sizes, int n_in,
                              void* d_out, int out_size) {
    const float4* bbox   = (const float4*)d_in[0];  // [1,4M,4] f32
    const float2* logits = (const float2*)d_in[1];  // [1,4M,2] f32
    const float4* sigma  = (const float4*)d_in[2];  // [1,4M,4] f32
    const float4* gt     = (const float4*)d_in[3];  // [1,4M,4] f32
    const int*    label  = (const int*)d_in[4];     // [1,4M] i32
    const int*    vidx   = (const int*)d_in[5];     // [V] i32
    float* out = (float*)d_out;
    int V = in_sizes[5];

    // Two loop iterations per thread (matching the proven R7 shape):
    // blocks such that grid*TPB*VPT*2 >= V.
    int blocks = (V + TPB * VPT * 2 - 1) / (TPB * VPT * 2);
    if (blocks > NBLK) blocks = NBLK;
    rpn_reduce_kernel<<<blocks, TPB>>>(bbox, logits, sigma, gt, label, vidx,
                                       out, V);
}

// round 16
// speedup vs baseline: 1.0313x; 1.0313x over previous
#include <cuda_runtime.h>

#define TPB 256
#define NBLK 2048
#define VPT 2

// Device globals (zero-initialized at load; the last block of each call
// resets them -> deterministic under graph replay).
// g_sums: [0]=class, [1]=bbox, [2]=sigma, [3]=neg, [4]=n_pos
__device__ double g_sums[5];
__device__ int    g_last_pos;   // stores lastp+1 (0 == none)
__device__ unsigned int g_done; // completion ticket counter

__inline__ __device__ float warp_sum_f(float v) {
    #pragma unroll
    for (int o = 16; o > 0; o >>= 1) v += __shfl_down_sync(0xffffffffu, v, o);
    return v;
}
__inline__ __device__ int warp_sum_i(int v) {
    #pragma unroll
    for (int o = 16; o > 0; o >>= 1) v += __shfl_down_sync(0xffffffffu, v, o);
    return v;
}
__inline__ __device__ int warp_max_i(int v) {
    #pragma unroll
    for (int o = 16; o > 0; o >>= 1) v = max(v, __shfl_down_sync(0xffffffffu, v, o));
    return v;
}

__global__ void rpn_reduce_kernel(const float4* __restrict__ bbox,   // [4M]
                                  const float2* __restrict__ logits, // [4M]
                                  const float4* __restrict__ sigma,  // [4M]
                                  const float4* __restrict__ gt,     // [4M]
                                  const int* __restrict__ label,     // [4M]
                                  const int* __restrict__ vidx,      // [V]
                                  float* __restrict__ out,
                                  int V) {
    const float EPS = 1e-10f;
    float acc_c = 0.0f, acc_b = 0.0f, acc_s = 0.0f, acc_n = 0.0f;
    int npos = 0, lastp = -1;

    const int stride = gridDim.x * TPB * VPT;
    int i0 = (blockIdx.x * TPB + threadIdx.x) * VPT;

    // Prime the index pipeline.
    int ia = 0, ib = 0;
    if (i0 + 1 < V) {
        int2 a2 = *reinterpret_cast<const int2*>(vidx + i0);
        ia = a2.x; ib = a2.y;
    } else if (i0 < V) {
        ia = vidx[i0]; ib = ia;
    }

    for (; i0 < V; i0 += stride) {
        bool live1 = (i0 + 1 < V);
        int a0 = ia, a1 = ib;

        // Issue all 10 gathers for this pair.
        int    lbl0 = label[a0],  lbl1 = label[a1];
        float2 lg0  = logits[a0], lg1  = logits[a1];
        float4 p0   = bbox[a0],   p1   = bbox[a1];
        float4 t0   = gt[a0],     t1   = gt[a1];
        float4 s0   = sigma[a0],  s1   = sigma[a1];

        // Prefetch next iteration's indices (overlaps with the math below).
        int inext = i0 + stride;
        if (inext + 1 < V) {
            int2 a2 = *reinterpret_cast<const int2*>(vidx + inext);
            ia = a2.x; ib = a2.y;
        } else if (inext < V) {
            ia = vidx[inext]; ib = ia;
        }

        #pragma unroll
        for (int j = 0; j < VPT; j++) {
            bool  live = (j == 0) ? true : live1;
            int   lbl  = (j == 0) ? lbl0 : lbl1;
            float2 lg  = (j == 0) ? lg0  : lg1;
            float4 p   = (j == 0) ? p0   : p1;
            float4 t   = (j == 0) ? t0   : t1;
            float4 s   = (j == 0) ? s0   : s1;

            bool pos = (lbl == 1);

            // -log_softmax at label (stable 2-class LSE)
            float m   = fmaxf(lg.x, lg.y);
            float d   = -fabsf(lg.x - lg.y);
            float lse = m + __logf(1.0f + __expf(d));
            float sel = pos ? lg.y : lg.x;
            float cls = lse - sel;

            float dx = p.x - t.x, dy = p.y - t.y, dz = p.z - t.z, dw = p.w - t.w;
            float e0 = EPS + s.x, e1 = EPS + s.y, e2 = EPS + s.z, e3 = EPS + s.w;
            float r0 = __fdividef(1.0f, e0), r1 = __fdividef(1.0f, e1),
                  r2 = __fdividef(1.0f, e2), r3 = __fdividef(1.0f, e3);

            float bsum = 0.5f * (dx * dx * r0 + dy * dy * r1 +
                                 dz * dz * r2 + dw * dw * r3);
            float lsum = 0.5f * (__logf(e0 * e1) + __logf(e2 * e3));
            float nsum = r0 + r1 + r2 + r3;

            if (live) {
                acc_c += cls;
                if (pos) {
                    acc_b += bsum;
                    acc_s += lsum;
                    npos++;
                    lastp = i0 + j;
                } else {
                    acc_n += nsum;
                }
            }
        }
    }

    // Block reduction in fp32 -> one double atomic per block per quantity.
    __shared__ float sh[4][TPB / 32];
    __shared__ int   shi[2][TPB / 32];
    int lane = threadIdx.x & 31;
    int wid  = threadIdx.x >> 5;

    acc_c = warp_sum_f(acc_c);
    acc_b = warp_sum_f(acc_b);
    acc_s = warp_sum_f(acc_s);
    acc_n = warp_sum_f(acc_n);
    npos  = warp_sum_i(npos);
    lastp = warp_max_i(lastp);
    if (lane == 0) {
        sh[0][wid] = acc_c; sh[1][wid] = acc_b;
        sh[2][wid] = acc_s; sh[3][wid] = acc_n;
        shi[0][wid] = npos; shi[1][wid] = lastp;
    }
    __syncthreads();
    if (wid == 0) {
        const int NW = TPB / 32;
        float c  = (lane < NW) ? sh[0][lane] : 0.0f;
        float b  = (lane < NW) ? sh[1][lane] : 0.0f;
        float s2 = (lane < NW) ? sh[2][lane] : 0.0f;
        float n2 = (lane < NW) ? sh[3][lane] : 0.0f;
        int np = (lane < NW) ? shi[0][lane] : 0;
        int lp = (lane < NW) ? shi[1][lane] : -1;
        c = warp_sum_f(c); b = warp_sum_f(b);
        s2 = warp_sum_f(s2); n2 = warp_sum_f(n2);
        np = warp_sum_i(np); lp = warp_max_i(lp);
        if (lane == 0) {
            atomicAdd(&g_sums[0], (double)c);
            atomicAdd(&g_sums[1], (double)b);
            atomicAdd(&g_sums[2], (double)s2);
            atomicAdd(&g_sums[3], (double)n2);
            atomicAdd(&g_sums[4], (double)np);
            atomicMax(&g_last_pos, lp + 1);  // lp+1 so 0 == "none"

            // Completion ticket: the LAST block finalizes.
            __threadfence();
            unsigned int ticket = atomicAdd(&g_done, 1u);
            if (ticket == gridDim.x - 1) {
                double fc = atomicAdd(&g_sums[0], 0.0);
                double fb = atomicAdd(&g_sums[1], 0.0);
                double fs = atomicAdd(&g_sums[2], 0.0);
                double fn = atomicAdd(&g_sums[3], 0.0);
                double npos_d = atomicAdd(&g_sums[4], 0.0);
                int lpf = atomicMax(&g_last_pos, 0) - 1;
                double nneg = (double)V - npos_d;

                out[0] = (float)(fc / (double)V);
                out[1] = (float)(fb / npos_d);
                out[2] = (float)(fs / npos_d);
                out[3] = (float)(fn / nneg);
                float sq = 0.0f;
                if (lpf >= 0) {
                    int a = vidx[lpf];
                    float4 pp = bbox[a];
                    float4 tt = gt[a];
                    float dx = pp.x - tt.x, dy = pp.y - tt.y,
                          dz = pp.z - tt.z, dw = pp.w - tt.w;
                    sq = 0.5f * (dx * dx + dy * dy + dz * dz + dw * dw);
                }
                out[4] = (float)((double)sq / npos_d);

                // Reset globals for the next (graph-replayed) call.
                g_sums[0] = 0.0; g_sums[1] = 0.0; g_sums[2] = 0.0;
                g_sums[3] = 0.0; g_sums[4] = 0.0;
                g_last_pos = 0;
                __threadfence();
                g_done = 0u;
            }
        }
    }
}

extern "C" void kernel_launch(void* const* d_in, const int* in_sizes, int n_in,
                              void* d_out, int out_size) {
    const float4* bbox   = (const float4*)d_in[0];  // [1,4M,4] f32
    const float2* logits = (const float2*)d_in[1];  // [1,4M,2] f32
    const float4* sigma  = (const float4*)d_in[2];  // [1,4M,4] f32
    const float4* gt     = (const float4*)d_in[3];  // [1,4M,4] f32
    const int*    label  = (const int*)d_in[4];     // [1,4M] i32
    const int*    vidx   = (const int*)d_in[5];     // [V] i32
    float* out = (float*)d_out;
    int V = in_sizes[5];

    int blocks = (V + TPB * VPT - 1) / (TPB * VPT);
    if (blocks > NBLK) blocks = NBLK;
    rpn_reduce_kernel<<<blocks, TPB>>>(bbox, logits, sigma, gt, label, vidx,
                                       out, V);
}

// round 17
// speedup vs baseline: 1.0426x; 1.0110x over previous
#include <cuda_runtime.h>

#define TPB 256
#define NBLK 2048
#define VPT 2

// Device globals (zero-initialized at load; the last block of each call
// resets them -> deterministic under graph replay).
// g_sums: [0]=class, [1]=bbox, [2]=sigma, [3]=neg, [4]=n_pos
__device__ double g_sums[5];
__device__ int    g_last_pos;   // stores lastp+1 (0 == none)
__device__ unsigned int g_done; // completion ticket counter

__inline__ __device__ float warp_sum_f(float v) {
    #pragma unroll
    for (int o = 16; o > 0; o >>= 1) v += __shfl_down_sync(0xffffffffu, v, o);
    return v;
}
__inline__ __device__ int warp_sum_i(int v) {
    #pragma unroll
    for (int o = 16; o > 0; o >>= 1) v += __shfl_down_sync(0xffffffffu, v, o);
    return v;
}
__inline__ __device__ int warp_max_i(int v) {
    #pragma unroll
    for (int o = 16; o > 0; o >>= 1) v = max(v, __shfl_down_sync(0xffffffffu, v, o));
    return v;
}

__global__ void rpn_reduce_kernel(const float4* __restrict__ bbox,   // [4M]
                                  const float2* __restrict__ logits, // [4M]
                                  const float4* __restrict__ sigma,  // [4M]
                                  const float4* __restrict__ gt,     // [4M]
                                  const int* __restrict__ label,     // [4M]
                                  const int* __restrict__ vidx,      // [V]
                                  float* __restrict__ out,
                                  int V) {
    const float EPS = 1e-10f;
    float acc_c = 0.0f, acc_b = 0.0f, acc_s = 0.0f, acc_n = 0.0f;
    int npos = 0, lastp = -1;

    const int stride = gridDim.x * TPB * VPT;
    int i0 = (blockIdx.x * TPB + threadIdx.x) * VPT;

    // Prime the index pipeline.
    int ia = 0, ib = 0;
    if (i0 + 1 < V) {
        int2 a2 = __ldcs(reinterpret_cast<const int2*>(vidx + i0));
        ia = a2.x; ib = a2.y;
    } else if (i0 < V) {
        ia = __ldcs(vidx + i0); ib = ia;
    }

    for (; i0 < V; i0 += stride) {
        bool live1 = (i0 + 1 < V);
        int a0 = ia, a1 = ib;

        // Issue all 10 gathers for this pair (streaming / evict-first:
        // single-use data, keep L1/L2 clean for the in-flight window).
        int    lbl0 = __ldcs(label + a0),   lbl1 = __ldcs(label + a1);
        float2 lg0  = __ldcs(logits + a0),  lg1  = __ldcs(logits + a1);
        float4 p0   = __ldcs(bbox + a0),    p1   = __ldcs(bbox + a1);
        float4 t0   = __ldcs(gt + a0),      t1   = __ldcs(gt + a1);
        float4 s0   = __ldcs(sigma + a0),   s1   = __ldcs(sigma + a1);

        // Prefetch next iteration's indices (overlaps with the math below).
        int inext = i0 + stride;
        if (inext + 1 < V) {
            int2 a2 = __ldcs(reinterpret_cast<const int2*>(vidx + inext));
            ia = a2.x; ib = a2.y;
        } else if (inext < V) {
            ia = __ldcs(vidx + inext); ib = ia;
        }

        #pragma unroll
        for (int j = 0; j < VPT; j++) {
            bool  live = (j == 0) ? true : live1;
            int   lbl  = (j == 0) ? lbl0 : lbl1;
            float2 lg  = (j == 0) ? lg0  : lg1;
            float4 p   = (j == 0) ? p0   : p1;
            float4 t   = (j == 0) ? t0   : t1;
            float4 s   = (j == 0) ? s0   : s1;

            bool pos = (lbl == 1);

            // -log_softmax at label (stable 2-class LSE)
            float m   = fmaxf(lg.x, lg.y);
            float d   = -fabsf(lg.x - lg.y);
            float lse = m + __logf(1.0f + __expf(d));
            float sel = pos ? lg.y : lg.x;
            float cls = lse - sel;

            float dx = p.x - t.x, dy = p.y - t.y, dz = p.z - t.z, dw = p.w - t.w;
            float e0 = EPS + s.x, e1 = EPS + s.y, e2 = EPS + s.z, e3 = EPS + s.w;
            float r0 = __fdividef(1.0f, e0), r1 = __fdividef(1.0f, e1),
                  r2 = __fdividef(1.0f, e2), r3 = __fdividef(1.0f, e3);

            float bsum = 0.5f * (dx * dx * r0 + dy * dy * r1 +
                                 dz * dz * r2 + dw * dw * r3);
            float lsum = 0.5f * (__logf(e0 * e1) + __logf(e2 * e3));
            float nsum = r0 + r1 + r2 + r3;

            if (live) {
                acc_c += cls;
                if (pos) {
                    acc_b += bsum;
                    acc_s += lsum;
                    npos++;
                    lastp = i0 + j;
                } else {
                    acc_n += nsum;
                }
            }
        }
    }

    // Block reduction in fp32 -> one double atomic per block per quantity.
    __shared__ float sh[4][TPB / 32];
    __shared__ int   shi[2][TPB / 32];
    int lane = threadIdx.x & 31;
    int wid  = threadIdx.x >> 5;

    acc_c = warp_sum_f(acc_c);
    acc_b = warp_sum_f(acc_b);
    acc_s = warp_sum_f(acc_s);
    acc_n = warp_sum_f(acc_n);
    npos  = warp_sum_i(npos);
    lastp = warp_max_i(lastp);
    if (lane == 0) {
        sh[0][wid] = acc_c; sh[1][wid] = acc_b;
        sh[2][wid] = acc_s; sh[3][wid] = acc_n;
        shi[0][wid] = npos; shi[1][wid] = lastp;
    }
    __syncthreads();
    if (wid == 0) {
        const int NW = TPB / 32;
        float c  = (lane < NW) ? sh[0][lane] : 0.0f;
        float b  = (lane < NW) ? sh[1][lane] : 0.0f;
        float s2 = (lane < NW) ? sh[2][lane] : 0.0f;
        float n2 = (lane < NW) ? sh[3][lane] : 0.0f;
        int np = (lane < NW) ? shi[0][lane] : 0;
        int lp = (lane < NW) ? shi[1][lane] : -1;
        c = warp_sum_f(c); b = warp_sum_f(b);
        s2 = warp_sum_f(s2); n2 = warp_sum_f(n2);
        np = warp_sum_i(np); lp = warp_max_i(lp);
        if (lane == 0) {
            atomicAdd(&g_sums[0], (double)c);
            atomicAdd(&g_sums[1], (double)b);
            atomicAdd(&g_sums[2], (double)s2);
            atomicAdd(&g_sums[3], (double)n2);
            atomicAdd(&g_sums[4], (double)np);
            atomicMax(&g_last_pos, lp + 1);  // lp+1 so 0 == "none"

            // Completion ticket: the LAST block finalizes.
            __threadfence();
            unsigned int ticket = atomicAdd(&g_done, 1u);
            if (ticket == gridDim.x - 1) {
                double fc = atomicAdd(&g_sums[0], 0.0);
                double fb = atomicAdd(&g_sums[1], 0.0);
                double fs = atomicAdd(&g_sums[2], 0.0);
                double fn = atomicAdd(&g_sums[3], 0.0);
                double npos_d = atomicAdd(&g_sums[4], 0.0);
                int lpf = atomicMax(&g_last_pos, 0) - 1;
                double nneg = (double)V - npos_d;

                out[0] = (float)(fc / (double)V);
                out[1] = (float)(fb / npos_d);
                out[2] = (float)(fs / npos_d);
                out[3] = (float)(fn / nneg);
                float sq = 0.0f;
                if (lpf >= 0) {
                    int a = vidx[lpf];
                    float4 pp = bbox[a];
                    float4 tt = gt[a];
                    float dx = pp.x - tt.x, dy = pp.y - tt.y,
                          dz = pp.z - tt.z, dw = pp.w - tt.w;
                    sq = 0.5f * (dx * dx + dy * dy + dz * dz + dw * dw);
                }
                out[4] = (float)((double)sq / npos_d);

                // Reset globals for the next (graph-replayed) call.
                g_sums[0] = 0.0; g_sums[1] = 0.0; g_sums[2] = 0.0;
                g_sums[3] = 0.0; g_sums[4] = 0.0;
                g_last_pos = 0;
                __threadfence();
                g_done = 0u;
            }
        }
    }
}

extern "C" void kernel_launch(void* const* d_in, const int* in_sizes, int n_in,
                              void* d_out, int out_size) {
    const float4* bbox   = (const float4*)d_in[0];  // [1,4M,4] f32
    const float2* logits = (const float2*)d_in[1];  // [1,4M,2] f32
    const float4* sigma  = (const float4*)d_in[2];  // [1,4M,4] f32
    const float4* gt     = (const float4*)d_in[3];  // [1,4M,4] f32
    const int*    label  = (const int*)d_in[4];     // [1,4M] i32
    const int*    vidx   = (const int*)d_in[5];     // [V] i32
    float* out = (float*)d_out;
    int V = in_sizes[5];

    int blocks = (V + TPB * VPT - 1) / (TPB * VPT);
    if (blocks > NBLK) blocks = NBLK;
    rpn_reduce_kernel<<<blocks, TPB>>>(bbox, logits, sigma, gt, label, vidx,
                                       out, V);
}